// round 2
// baseline (speedup 1.0000x reference)
#include <cuda_runtime.h>
#include <cuda_bf16.h>

#define N_NODES 50000
#define N_EDGES 800000
#define D 128

// -------- device scratch (no runtime allocation allowed) --------
__device__ int   g_cnt[N_NODES];
__device__ int   g_off[N_NODES + 1];
__device__ int   g_pos[N_NODES];
__device__ int   g_src_sorted[N_EDGES];
__device__ float g_mean[(size_t)N_NODES * D];
__device__ float g_h0[(size_t)N_NODES * D];
__device__ float g_h1[(size_t)N_NODES * D];
__device__ double g_sum[D];
__device__ double g_sumsq[D];
__device__ float g_bn_scale[D];
__device__ float g_bn_shift[D];

// -------- CSR build --------
__global__ void zero_kernel() {
    int i = blockIdx.x * blockDim.x + threadIdx.x;
    if (i < N_NODES) g_cnt[i] = 0;
    if (i < D) { g_sum[i] = 0.0; g_sumsq[i] = 0.0; }
}

__global__ void hist_kernel(const int* __restrict__ dst) {
    int e = blockIdx.x * blockDim.x + threadIdx.x;
    if (e < N_EDGES) atomicAdd(&g_cnt[dst[e]], 1);
}

// single-block exclusive scan over 50000 counts
__global__ void scan_kernel() {
    __shared__ int s[1024];
    const int t = threadIdx.x;
    const int CH = (N_NODES + 1023) / 1024;  // 49
    int base = t * CH;
    int sum = 0;
    for (int i = 0; i < CH; i++) {
        int idx = base + i;
        if (idx < N_NODES) sum += g_cnt[idx];
    }
    s[t] = sum;
    __syncthreads();
    for (int offset = 1; offset < 1024; offset <<= 1) {
        int v = (t >= offset) ? s[t - offset] : 0;
        __syncthreads();
        s[t] += v;
        __syncthreads();
    }
    int run = (t == 0) ? 0 : s[t - 1];
    for (int i = 0; i < CH; i++) {
        int idx = base + i;
        if (idx < N_NODES) {
            g_off[idx] = run;
            g_pos[idx] = run;
            run += g_cnt[idx];
        }
    }
    if (t == 1023) g_off[N_NODES] = s[1023];
}

__global__ void scatter_kernel(const int* __restrict__ src,
                               const int* __restrict__ dst) {
    int e = blockIdx.x * blockDim.x + threadIdx.x;
    if (e < N_EDGES) {
        int p = atomicAdd(&g_pos[dst[e]], 1);
        g_src_sorted[p] = src[e];
    }
}

// -------- mean aggregation: one warp per node, lane = 4 feature floats --------
__global__ void agg_kernel(const float* __restrict__ h, float* __restrict__ out) {
    int gw = (blockIdx.x * blockDim.x + threadIdx.x) >> 5;
    int lane = threadIdx.x & 31;
    if (gw >= N_NODES) return;
    int beg = g_off[gw];
    int end = g_off[gw + 1];
    float4 acc = make_float4(0.f, 0.f, 0.f, 0.f);
    int i = beg;
    // 2x unroll for a bit of MLP
    for (; i + 1 < end; i += 2) {
        int s0 = g_src_sorted[i];
        int s1 = g_src_sorted[i + 1];
        float4 v0 = *(const float4*)(h + (size_t)s0 * D + lane * 4);
        float4 v1 = *(const float4*)(h + (size_t)s1 * D + lane * 4);
        acc.x += v0.x + v1.x;
        acc.y += v0.y + v1.y;
        acc.z += v0.z + v1.z;
        acc.w += v0.w + v1.w;
    }
    if (i < end) {
        int s0 = g_src_sorted[i];
        float4 v0 = *(const float4*)(h + (size_t)s0 * D + lane * 4);
        acc.x += v0.x; acc.y += v0.y; acc.z += v0.z; acc.w += v0.w;
    }
    float inv = 1.0f / fmaxf((float)(end - beg), 1.0f);
    acc.x *= inv; acc.y *= inv; acc.z *= inv; acc.w *= inv;
    *(float4*)(out + (size_t)gw * D + lane * 4) = acc;
}

// -------- fused GEMM: out = A0 @ Wl^T + A1 @ Wr^T + b, optional ReLU --------
// block tile: 64 rows x 128 cols, 256 threads, per-thread 8x4 accumulators.
// dyn smem: As[64][128] (natural layout) + Ws[128][128] (transposed, Ws[k][j]).
template <bool RELU>
__global__ void __launch_bounds__(256, 2)
gemm_kernel(const float* __restrict__ A0, const float* __restrict__ A1,
            const float* __restrict__ Wl, const float* __restrict__ Wr,
            const float* __restrict__ bias, float* __restrict__ out) {
    extern __shared__ float smem[];
    float* As = smem;             // 64*128 = 8192 floats
    float* Ws = smem + 64 * D;    // 128*128 = 16384 floats

    const int tid = threadIdx.x;
    const int trow = tid >> 5;    // 0..7
    const int tcol = tid & 31;    // 0..31
    const int row0 = blockIdx.x * 64;

    float acc[8][4];
#pragma unroll
    for (int i = 0; i < 8; i++)
#pragma unroll
        for (int j = 0; j < 4; j++) acc[i][j] = 0.f;

    for (int phase = 0; phase < 2; phase++) {
        const float* A = phase ? A1 : A0;
        const float* W = phase ? Wr : Wl;
        __syncthreads();  // protect smem of previous phase
        // load A tile: 64 rows x 128 cols, coalesced; natural layout in smem
#pragma unroll
        for (int it = 0; it < 8; it++) {
            int idx = tid + it * 256;     // 0..2047 float4 slots
            int kq = idx & 31;            // float4 group along k
            int r = idx >> 5;             // row in tile
            int row = row0 + r;
            float4 v = make_float4(0.f, 0.f, 0.f, 0.f);
            if (row < N_NODES) v = *(const float4*)(A + (size_t)row * D + kq * 4);
            *(float4*)(As + r * D + kq * 4) = v;
        }
        // load W transposed: Ws[k][j] = W[j][k]. j fastest over threads:
        // smem writes conflict-free; gmem reads hit L2 (W is 64KB, hot).
#pragma unroll
        for (int it = 0; it < 16; it++) {
            int idx = tid + it * 256;     // 0..4095
            int j = idx & 127;            // output column
            int kq = idx >> 7;            // 0..31
            float4 v = *(const float4*)(W + (size_t)j * D + kq * 4);
            Ws[(kq * 4 + 0) * D + j] = v.x;
            Ws[(kq * 4 + 1) * D + j] = v.y;
            Ws[(kq * 4 + 2) * D + j] = v.z;
            Ws[(kq * 4 + 3) * D + j] = v.w;
        }
        __syncthreads();

#pragma unroll 4
        for (int k = 0; k < D; k++) {
            float4 w = *(const float4*)(Ws + k * D + tcol * 4);
            float a[8];
#pragma unroll
            for (int i = 0; i < 8; i++) a[i] = As[(trow * 8 + i) * D + k];
#pragma unroll
            for (int i = 0; i < 8; i++) {
                acc[i][0] = fmaf(a[i], w.x, acc[i][0]);
                acc[i][1] = fmaf(a[i], w.y, acc[i][1]);
                acc[i][2] = fmaf(a[i], w.z, acc[i][2]);
                acc[i][3] = fmaf(a[i], w.w, acc[i][3]);
            }
        }
    }

    // epilogue
    float4 b4 = *(const float4*)(bias + tcol * 4);
#pragma unroll
    for (int i = 0; i < 8; i++) {
        int row = row0 + trow * 8 + i;
        if (row < N_NODES) {
            float4 v;
            v.x = acc[i][0] + b4.x;
            v.y = acc[i][1] + b4.y;
            v.z = acc[i][2] + b4.z;
            v.w = acc[i][3] + b4.w;
            if (RELU) {
                v.x = fmaxf(v.x, 0.f); v.y = fmaxf(v.y, 0.f);
                v.z = fmaxf(v.z, 0.f); v.w = fmaxf(v.w, 0.f);
            }
            *(float4*)(out + (size_t)row * D + tcol * 4) = v;
        }
    }
}

// -------- batchnorm --------
__global__ void bn_stats(const float* __restrict__ h) {
    int col = threadIdx.x;        // 128 threads
    int r0 = blockIdx.x * 250;    // 200 blocks x 250 rows
    float s = 0.f, s2 = 0.f;
    for (int r = r0; r < r0 + 250; r++) {
        float v = h[(size_t)r * D + col];
        s += v;
        s2 += v * v;
    }
    atomicAdd(&g_sum[col], (double)s);
    atomicAdd(&g_sumsq[col], (double)s2);
}

__global__ void bn_finalize(const float* __restrict__ gamma,
                            const float* __restrict__ beta) {
    int c = threadIdx.x;
    double mu = g_sum[c] / (double)N_NODES;
    double var = g_sumsq[c] / (double)N_NODES - mu * mu;
    float inv = rsqrtf((float)var + 1e-5f);
    float sc = inv * gamma[c];
    g_bn_scale[c] = sc;
    g_bn_shift[c] = beta[c] - (float)mu * sc;
}

__global__ void bn_apply(float* __restrict__ h) {
    int i = blockIdx.x * blockDim.x + threadIdx.x;
    if (i < N_NODES * D) {
        int col = i & (D - 1);
        float v = fmaf(h[i], g_bn_scale[col], g_bn_shift[col]);
        h[i] = fmaxf(v, 0.f);
    }
}

// -------- launch --------
extern "C" void kernel_launch(void* const* d_in, const int* in_sizes, int n_in,
                              void* d_out, int out_size) {
    const float* x     = (const float*)d_in[0];
    const int*   ei    = (const int*)d_in[1];
    const float* Wl0   = (const float*)d_in[2];
    const float* bl0   = (const float*)d_in[3];
    const float* Wr0   = (const float*)d_in[4];
    const float* Wl1   = (const float*)d_in[5];
    const float* bl1   = (const float*)d_in[6];
    const float* Wr1   = (const float*)d_in[7];
    const float* Wl2   = (const float*)d_in[8];
    const float* bl2   = (const float*)d_in[9];
    const float* Wr2   = (const float*)d_in[10];
    const float* gamma = (const float*)d_in[11];
    const float* beta  = (const float*)d_in[12];
    float* out = (float*)d_out;

    const int* srcp = ei;
    const int* dstp = ei + N_EDGES;

    const int SMEM = (64 * D + D * D) * sizeof(float);  // 96 KB
    cudaFuncSetAttribute(gemm_kernel<true>,
                         cudaFuncAttributeMaxDynamicSharedMemorySize, SMEM);
    cudaFuncSetAttribute(gemm_kernel<false>,
                         cudaFuncAttributeMaxDynamicSharedMemorySize, SMEM);

    const int EB = (N_EDGES + 255) / 256;         // 3125
    const int AGGB = (N_NODES * 32 + 255) / 256;  // 6250
    const int GB = (N_NODES + 63) / 64;           // 782

    zero_kernel<<<(N_NODES + 255) / 256, 256>>>();
    hist_kernel<<<EB, 256>>>(dstp);
    scan_kernel<<<1, 1024>>>();
    scatter_kernel<<<EB, 256>>>(srcp, dstp);

    // layer 0: h0 = relu(mean(x) @ Wl0^T + bl0 + x @ Wr0^T)
    agg_kernel<<<AGGB, 256>>>(x, g_mean);
    gemm_kernel<true><<<GB, 256, SMEM>>>(g_mean, x, Wl0, Wr0, bl0, g_h0);

    // layer 1: h1 = mean(h0) @ Wl1^T + bl1 + h0 @ Wr1^T
    agg_kernel<<<AGGB, 256>>>(g_h0, g_mean);
    gemm_kernel<false><<<GB, 256, SMEM>>>(g_mean, g_h0, Wl1, Wr1, bl1, g_h1);

    // h1 = relu(batchnorm(h1))
    bn_stats<<<200, 128>>>(g_h1);
    bn_finalize<<<1, 128>>>(gamma, beta);
    bn_apply<<<(N_NODES * D + 255) / 256, 256>>>(g_h1);

    // layer 2: out = mean(h1) @ Wl2^T + bl2 + h1 @ Wr2^T
    agg_kernel<<<AGGB, 256>>>(g_h1, g_mean);
    gemm_kernel<false><<<GB, 256, SMEM>>>(g_mean, g_h1, Wl2, Wr2, bl2, out);
}